// round 6
// baseline (speedup 1.0000x reference)
#include <cuda_runtime.h>
#include <cuda_bf16.h>
#include <cstdint>

#define T 1024
#define H 1024
#define F 768
#define E 32
#define K 4

#define KC 32            // k elems per chunk
#define PITCH_B 80       // bytes per smem row -> conflict-free ldmatrix
#define BSZ (128 * PITCH_B)          /* one B plane: 10240 */
#define BUF_STRIDE (2 * BSZ)         /* hi+lo planes: 20480 */
#define SMEM_TOTAL (2 * BUF_STRIDE)  /* double buffered: 40960 */
#define NC1 (H / KC)     // 32
#define NC2 (F / KC)     // 24

// ---------------- scratch ----------------
__device__ float    g_topk_w[T * K];
__device__ int      g_topk_id[T * K];
__device__ int      g_offset[E + 1];
__device__ int      g_assign_token[T * K];
__device__ int      g_row_of[T * K];
__device__ uint32_t g_hs_pk[(size_t)T * H];       // packed bf16 hi|lo<<16
__device__ uint32_t g_act_pk[(size_t)T * K * F];  // packed bf16 hi|lo<<16
__device__ float    g_y[(size_t)T * K * H];

// ---------------- helpers ----------------
__device__ __forceinline__ uint32_t smem_u32(const void* p) {
    uint32_t a;
    asm("{ .reg .u64 t; cvta.to.shared.u64 t, %1; cvt.u32.u64 %0, t; }" : "=r"(a) : "l"(p));
    return a;
}

#define LDM4(r, addr) \
    asm volatile("ldmatrix.sync.aligned.m8n8.x4.shared.b16 {%0,%1,%2,%3}, [%4];" \
        : "=r"((r)[0]), "=r"((r)[1]), "=r"((r)[2]), "=r"((r)[3]) : "r"(addr))

#define MMA16816(d, a, b0, b1) \
    asm volatile("mma.sync.aligned.m16n8k16.row.col.f32.bf16.bf16.f32 " \
        "{%0,%1,%2,%3}, {%4,%5,%6,%7}, {%8,%9}, {%0,%1,%2,%3};" \
        : "+f"((d)[0]), "+f"((d)[1]), "+f"((d)[2]), "+f"((d)[3]) \
        : "r"((a)[0]), "r"((a)[1]), "r"((a)[2]), "r"((a)[3]), "r"(b0), "r"(b1))

// split float4 -> bf16 hi pair-packed + lo pair-packed
__device__ __forceinline__ void cvt_split4(float4 v, uint2& hi, uint2& lo) {
    uint32_t h01, h23, l01, l23;
    asm("cvt.rn.bf16x2.f32 %0, %1, %2;" : "=r"(h01) : "f"(v.y), "f"(v.x));
    asm("cvt.rn.bf16x2.f32 %0, %1, %2;" : "=r"(h23) : "f"(v.w), "f"(v.z));
    float h0 = __uint_as_float(h01 << 16), h1 = __uint_as_float(h01 & 0xFFFF0000u);
    float h2 = __uint_as_float(h23 << 16), h3 = __uint_as_float(h23 & 0xFFFF0000u);
    asm("cvt.rn.bf16x2.f32 %0, %1, %2;" : "=r"(l01) : "f"(v.y - h1), "f"(v.x - h0));
    asm("cvt.rn.bf16x2.f32 %0, %1, %2;" : "=r"(l23) : "f"(v.w - h3), "f"(v.z - h2));
    hi = make_uint2(h01, h23);
    lo = make_uint2(l01, l23);
}

__device__ __forceinline__ uint32_t pack_hl(float a) {
    __nv_bfloat16 h = __float2bfloat16(a);
    float hf = __bfloat162float(h);
    __nv_bfloat16 l = __float2bfloat16(a - hf);
    return (uint32_t)__bfloat16_as_ushort(h) | ((uint32_t)__bfloat16_as_ushort(l) << 16);
}

__device__ __forceinline__ float silu(float x) { return x / (1.f + __expf(-x)); }

// build A hi/lo fragments for one m16k16 tile directly from packed global
// p00/p01: row r cols (c,c+1)/(c+8,c+9); p10/p11: row r+8 same cols
__device__ __forceinline__ void a_frag(const uint32_t* r0p, const uint32_t* r8p,
                                       int col, uint32_t* ah, uint32_t* al) {
    uint2 p00 = *(const uint2*)(r0p + col);
    uint2 p01 = *(const uint2*)(r0p + col + 8);
    uint2 p10 = *(const uint2*)(r8p + col);
    uint2 p11 = *(const uint2*)(r8p + col + 8);
    ah[0] = __byte_perm(p00.x, p00.y, 0x5410); al[0] = __byte_perm(p00.x, p00.y, 0x7632);
    ah[1] = __byte_perm(p10.x, p10.y, 0x5410); al[1] = __byte_perm(p10.x, p10.y, 0x7632);
    ah[2] = __byte_perm(p01.x, p01.y, 0x5410); al[2] = __byte_perm(p01.x, p01.y, 0x7632);
    ah[3] = __byte_perm(p11.x, p11.y, 0x5410); al[3] = __byte_perm(p11.x, p11.y, 0x7632);
}

// ---------------- hs preconvert ----------------
__global__ void hs_convert_kernel(const float* __restrict__ hs) {
    int i = blockIdx.x * blockDim.x + threadIdx.x;
    float4 v = *(const float4*)(hs + (size_t)i * 4);
    uint4 p;
    p.x = pack_hl(v.x); p.y = pack_hl(v.y); p.z = pack_hl(v.z); p.w = pack_hl(v.w);
    *(uint4*)(g_hs_pk + (size_t)i * 4) = p;
}

// ---------------- router ----------------
__global__ void router_kernel(const float* __restrict__ hs,
                              const float* __restrict__ gw) {
    int warp = (blockIdx.x * blockDim.x + threadIdx.x) >> 5;
    int lane = threadIdx.x & 31;
    if (warp >= T) return;

    const float4* x4 = (const float4*)(hs + (size_t)warp * H);
    const float4* g4 = (const float4*)(gw + (size_t)lane * H);
    float acc = 0.f;
#pragma unroll 4
    for (int i = 0; i < H / 4; i++) {
        float4 xv = x4[i];
        float4 gv = g4[i];
        acc += xv.x * gv.x + xv.y * gv.y + xv.z * gv.z + xv.w * gv.w;
    }
    float m = acc;
#pragma unroll
    for (int o = 16; o; o >>= 1) m = fmaxf(m, __shfl_xor_sync(0xffffffffu, m, o));
    float p = __expf(acc - m);
    float s = p;
#pragma unroll
    for (int o = 16; o; o >>= 1) s += __shfl_xor_sync(0xffffffffu, s, o);
    float prob = p / s;

    float cur = prob;
    float wv[K];
    int   wid[K];
#pragma unroll
    for (int k = 0; k < K; k++) {
        float v = cur;
        int who = lane;
#pragma unroll
        for (int o = 16; o; o >>= 1) {
            float ov = __shfl_xor_sync(0xffffffffu, v, o);
            int   oi = __shfl_xor_sync(0xffffffffu, who, o);
            if (ov > v || (ov == v && oi < who)) { v = ov; who = oi; }
        }
        wv[k] = v;
        wid[k] = who;
        if (lane == who) cur = -1.f;
    }
    if (lane == 0) {
        float ws = wv[0] + wv[1] + wv[2] + wv[3];
        float inv = 1.f / ws;
#pragma unroll
        for (int k = 0; k < K; k++) {
            g_topk_w[warp * K + k]  = wv[k] * inv;
            g_topk_id[warp * K + k] = wid[k];
        }
    }
}

// ---------------- bucket: count + scan + scatter in one block ----------------
__global__ void bucket_kernel() {
    __shared__ int cnt[E];
    __shared__ int curp[E];
    __shared__ int offp[E + 1];
    int t = threadIdx.x;
    if (t < E) cnt[t] = 0;
    __syncthreads();
    int ids[K];
#pragma unroll
    for (int k = 0; k < K; k++) {
        ids[k] = g_topk_id[t * K + k];
        atomicAdd(&cnt[ids[k]], 1);
    }
    __syncthreads();
    if (t == 0) {
        int a = 0;
        for (int e = 0; e < E; e++) { offp[e] = a; curp[e] = a; a += cnt[e]; }
        offp[E] = a;
    }
    __syncthreads();
#pragma unroll
    for (int k = 0; k < K; k++) {
        int pos = atomicAdd(&curp[ids[k]], 1);
        g_assign_token[pos] = t;
        g_row_of[t * K + k] = pos;
    }
    if (t <= E) g_offset[t] = offp[t];
}

// ================= GEMM1 (HMMA bf16x3, A direct-from-global) =================
__global__ __launch_bounds__(256) void gemm1_mma(const float* __restrict__ w1) {
    const int e  = blockIdx.y >> 3;
    const int mt = blockIdx.y & 7;
    const int rbeg = g_offset[e], rend = g_offset[e + 1];
    const int row0 = rbeg + mt * 128;
    if (row0 >= rend) return;
    const int fbase = blockIdx.x * 64;

    extern __shared__ __align__(16) char smem[];

    const int tid = threadIdx.x, lane = tid & 31;
    const int wm = (tid >> 5) & 3, wn = tid >> 7;

    // per-thread A row pointers into packed hs (2 m16 frags x rows r, r+8)
    const uint32_t* ar[2][2];
#pragma unroll
    for (int i = 0; i < 2; i++) {
        int rb = row0 + wm * 32 + i * 16 + (lane >> 2);
        int r0 = rb < rend ? rb : rbeg;
        int r8 = rb + 8 < rend ? rb + 8 : rbeg;
        ar[i][0] = g_hs_pk + (size_t)g_assign_token[r0] * H;
        ar[i][1] = g_hs_pk + (size_t)g_assign_token[r8] * H;
    }
    const int acol = 2 * (lane & 3);

    // B-load roles: 128 interleaved B-rows x 8 quads of w1 fp32
    const float* bptr[4];
    uint32_t boff[4];
#pragma unroll
    for (int i = 0; i < 4; i++) {
        int unit = tid + i * 256;
        int n = unit >> 3, q = unit & 7;
        int j = n >> 1, s = n & 1;
        size_t grow = (size_t)e * (2 * F) + (s ? F : 0) + fbase + j;
        bptr[i] = w1 + grow * H + q * 4;
        boff[i] = (uint32_t)(n * PITCH_B + q * 8);
    }

    const uint32_t base = smem_u32(smem);

    float acc[16][4];
#pragma unroll
    for (int i = 0; i < 16; i++)
#pragma unroll
        for (int j = 0; j < 4; j++) acc[i][j] = 0.f;

    float4 rB[4];
#pragma unroll
    for (int i = 0; i < 4; i++) rB[i] = *(const float4*)bptr[i];
#pragma unroll
    for (int i = 0; i < 4; i++) {
        uint2 hi, lo;
        cvt_split4(rB[i], hi, lo);
        *(uint2*)(smem + boff[i]) = hi;
        *(uint2*)(smem + BSZ + boff[i]) = lo;
    }
    __syncthreads();

    for (int c = 0; c < NC1; c++) {
        const uint32_t cb = base + (c & 1) * BUF_STRIDE;
        char* nbp = smem + ((c + 1) & 1) * BUF_STRIDE;

        if (c + 1 < NC1) {
#pragma unroll
            for (int i = 0; i < 4; i++) rB[i] = *(const float4*)(bptr[i] + (c + 1) * KC);
        }

#pragma unroll
        for (int ks = 0; ks < 2; ks++) {
            const int kk = c * KC + ks * 16;
            // A fragments straight from global packed
            uint32_t ah[2][4], al[2][4];
#pragma unroll
            for (int i = 0; i < 2; i++)
                a_frag(ar[i][0] + kk, ar[i][1] + kk, acol, ah[i], al[i]);
            // B fragments via ldmatrix
            const uint32_t kb = ks * 32;
            const uint32_t lrow = (lane & 15), lcol = (lane >> 4) * 16;
            uint32_t bh[4][4], bl[4][4];
#pragma unroll
            for (int j2 = 0; j2 < 4; j2++) {
                uint32_t off = (uint32_t)((wn * 64 + j2 * 16 + lrow) * PITCH_B) + lcol + kb;
                LDM4(bh[j2], cb + off);
                LDM4(bl[j2], cb + BSZ + off);
            }
            // pass-major MMAs
#pragma unroll
            for (int i = 0; i < 2; i++)
#pragma unroll
                for (int jt = 0; jt < 8; jt++) {
                    int j2 = jt >> 1, hsel = jt & 1;
                    MMA16816(acc[i * 8 + jt], ah[i], bh[j2][hsel], bh[j2][2 + hsel]);
                }
#pragma unroll
            for (int i = 0; i < 2; i++)
#pragma unroll
                for (int jt = 0; jt < 8; jt++) {
                    int j2 = jt >> 1, hsel = jt & 1;
                    MMA16816(acc[i * 8 + jt], ah[i], bl[j2][hsel], bl[j2][2 + hsel]);
                }
#pragma unroll
            for (int i = 0; i < 2; i++)
#pragma unroll
                for (int jt = 0; jt < 8; jt++) {
                    int j2 = jt >> 1, hsel = jt & 1;
                    MMA16816(acc[i * 8 + jt], al[i], bh[j2][hsel], bh[j2][2 + hsel]);
                }
        }

        if (c + 1 < NC1) {
#pragma unroll
            for (int i = 0; i < 4; i++) {
                uint2 hi, lo;
                cvt_split4(rB[i], hi, lo);
                *(uint2*)(nbp + boff[i]) = hi;
                *(uint2*)(nbp + BSZ + boff[i]) = lo;
            }
        }
        __syncthreads();
    }

    // epilogue: (c0,c1)=(g,u) row r1; (c2,c3)=(g,u) row r1+8
#pragma unroll
    for (int i = 0; i < 2; i++)
#pragma unroll
        for (int jt = 0; jt < 8; jt++) {
            float* d = acc[i * 8 + jt];
            int f = fbase + wn * 32 + jt * 4 + (lane & 3);
            int r1 = row0 + wm * 32 + i * 16 + (lane >> 2);
            float a0 = silu(d[0]) * d[1];
            float a1 = silu(d[2]) * d[3];
            if (r1 < rend)     g_act_pk[(size_t)r1 * F + f] = pack_hl(a0);
            if (r1 + 8 < rend) g_act_pk[(size_t)(r1 + 8) * F + f] = pack_hl(a1);
        }
}

// ================= GEMM2 (HMMA bf16x3, A direct-from-global) =================
__global__ __launch_bounds__(256) void gemm2_mma(const float* __restrict__ w2) {
    const int e  = blockIdx.y >> 3;
    const int mt = blockIdx.y & 7;
    const int rbeg = g_offset[e], rend = g_offset[e + 1];
    const int row0 = rbeg + mt * 128;
    if (row0 >= rend) return;
    const int hbase = blockIdx.x * 128;

    extern __shared__ __align__(16) char smem[];

    const int tid = threadIdx.x, lane = tid & 31;
    const int wm = (tid >> 5) & 3, wn = tid >> 7;

    const uint32_t* ar[2][2];
#pragma unroll
    for (int i = 0; i < 2; i++) {
        int rb = row0 + wm * 32 + i * 16 + (lane >> 2);
        int r0 = rb < rend ? rb : rbeg;
        int r8 = rb + 8 < rend ? rb + 8 : rbeg;
        ar[i][0] = g_act_pk + (size_t)r0 * F;
        ar[i][1] = g_act_pk + (size_t)r8 * F;
    }
    const int acol = 2 * (lane & 3);

    const float* bptr[4];
    uint32_t boff[4];
#pragma unroll
    for (int i = 0; i < 4; i++) {
        int unit = tid + i * 256;
        int n = unit >> 3, q = unit & 7;
        bptr[i] = w2 + ((size_t)e * H + hbase + n) * F + q * 4;
        boff[i] = (uint32_t)(n * PITCH_B + q * 8);
    }

    const uint32_t base = smem_u32(smem);

    float acc[16][4];
#pragma unroll
    for (int i = 0; i < 16; i++)
#pragma unroll
        for (int j = 0; j < 4; j++) acc[i][j] = 0.f;

    float4 rB[4];
#pragma unroll
    for (int i = 0; i < 4; i++) rB[i] = *(const float4*)bptr[i];
#pragma unroll
    for (int i = 0; i < 4; i++) {
        uint2 hi, lo;
        cvt_split4(rB[i], hi, lo);
        *(uint2*)(smem + boff[i]) = hi;
        *(uint2*)(smem + BSZ + boff[i]) = lo;
    }
    __syncthreads();

    for (int c = 0; c < NC2; c++) {
        const uint32_t cb = base + (c & 1) * BUF_STRIDE;
        char* nbp = smem + ((c + 1) & 1) * BUF_STRIDE;

        if (c + 1 < NC2) {
#pragma unroll
            for (int i = 0; i < 4; i++) rB[i] = *(const float4*)(bptr[i] + (c + 1) * KC);
        }

#pragma unroll
        for (int ks = 0; ks < 2; ks++) {
            const int kk = c * KC + ks * 16;
            uint32_t ah[2][4], al[2][4];
#pragma unroll
            for (int i = 0; i < 2; i++)
                a_frag(ar[i][0] + kk, ar[i][1] + kk, acol, ah[i], al[i]);
            const uint32_t kb = ks * 32;
            const uint32_t lrow = (lane & 15), lcol = (lane >> 4) * 16;
            uint32_t bh[4][4], bl[4][4];
#pragma unroll
            for (int j2 = 0; j2 < 4; j2++) {
                uint32_t off = (uint32_t)((wn * 64 + j2 * 16 + lrow) * PITCH_B) + lcol + kb;
                LDM4(bh[j2], cb + off);
                LDM4(bl[j2], cb + BSZ + off);
            }
#pragma unroll
            for (int i = 0; i < 2; i++)
#pragma unroll
                for (int jt = 0; jt < 8; jt++) {
                    int j2 = jt >> 1, hsel = jt & 1;
                    MMA16816(acc[i * 8 + jt], ah[i], bh[j2][hsel], bh[j2][2 + hsel]);
                }
#pragma unroll
            for (int i = 0; i < 2; i++)
#pragma unroll
                for (int jt = 0; jt < 8; jt++) {
                    int j2 = jt >> 1, hsel = jt & 1;
                    MMA16816(acc[i * 8 + jt], ah[i], bl[j2][hsel], bl[j2][2 + hsel]);
                }
#pragma unroll
            for (int i = 0; i < 2; i++)
#pragma unroll
                for (int jt = 0; jt < 8; jt++) {
                    int j2 = jt >> 1, hsel = jt & 1;
                    MMA16816(acc[i * 8 + jt], al[i], bh[j2][hsel], bh[j2][2 + hsel]);
                }
        }

        if (c + 1 < NC2) {
#pragma unroll
            for (int i = 0; i < 4; i++) {
                uint2 hi, lo;
                cvt_split4(rB[i], hi, lo);
                *(uint2*)(nbp + boff[i]) = hi;
                *(uint2*)(nbp + BSZ + boff[i]) = lo;
            }
        }
        __syncthreads();
    }

#pragma unroll
    for (int i = 0; i < 2; i++)
#pragma unroll
        for (int jt = 0; jt < 8; jt++) {
            float* d = acc[i * 8 + jt];
            int hcol = hbase + wn * 64 + jt * 8 + 2 * (lane & 3);
            int r1 = row0 + wm * 32 + i * 16 + (lane >> 2);
            if (r1 < rend)
                *(float2*)(g_y + (size_t)r1 * H + hcol) = make_float2(d[0], d[1]);
            if (r1 + 8 < rend)
                *(float2*)(g_y + (size_t)(r1 + 8) * H + hcol) = make_float2(d[2], d[3]);
        }
}

// ---------------- gather ----------------
__global__ void gather_kernel(float* __restrict__ out) {
    int t = blockIdx.x;
    __shared__ float ws[K];
    __shared__ int   rs[K];
    if (threadIdx.x < K) {
        ws[threadIdx.x] = g_topk_w[t * K + threadIdx.x];
        rs[threadIdx.x] = g_row_of[t * K + threadIdx.x];
    }
    __syncthreads();
    int h = threadIdx.x * 4;
    float4 acc = make_float4(0.f, 0.f, 0.f, 0.f);
#pragma unroll
    for (int k = 0; k < K; k++) {
        float4 v = *(const float4*)(g_y + (size_t)rs[k] * H + h);
        float w = ws[k];
        acc.x += w * v.x;
        acc.y += w * v.y;
        acc.z += w * v.z;
        acc.w += w * v.w;
    }
    *(float4*)(out + (size_t)t * H + h) = acc;
}

extern "C" void kernel_launch(void* const* d_in, const int* in_sizes, int n_in,
                              void* d_out, int out_size) {
    const float* hs = (const float*)d_in[0];
    const float* gw = (const float*)d_in[1];
    const float* w1 = (const float*)d_in[2];
    const float* w2 = (const float*)d_in[3];
    float* out = (float*)d_out;

    static bool attr_done = false;
    if (!attr_done) {
        cudaFuncSetAttribute(gemm1_mma, cudaFuncAttributeMaxDynamicSharedMemorySize, SMEM_TOTAL);
        cudaFuncSetAttribute(gemm2_mma, cudaFuncAttributeMaxDynamicSharedMemorySize, SMEM_TOTAL);
        attr_done = true;
    }

    hs_convert_kernel<<<T * H / 4 / 256, 256>>>(hs);
    router_kernel<<<T / 4, 128>>>(hs, gw);
    bucket_kernel<<<1, 1024>>>();
    gemm1_mma<<<dim3(F / 64, E * 8), 256, SMEM_TOTAL>>>(w1);
    gemm2_mma<<<dim3(H / 128, E * 8), 256, SMEM_TOTAL>>>(w2);
    gather_kernel<<<T, 256>>>(out);
}

// round 7
// speedup vs baseline: 1.2530x; 1.2530x over previous
#include <cuda_runtime.h>
#include <cuda_bf16.h>
#include <cstdint>

#define T 1024
#define H 1024
#define F 768
#define E 32
#define K 4

#define KC 32            // k elems per chunk
#define PITCH_B 80       // bytes per smem row -> conflict-free ldmatrix
#define PLANE (128 * PITCH_B)        /* 10240 */
#define BUF_STRIDE (4 * PLANE)       /* Ah, Al, Bh, Bl */
#define SMEM_TOTAL (2 * BUF_STRIDE)  /* 81920 */
#define NC1 (H / KC)     // 32
#define NC2 (F / KC)     // 24

// ---------------- scratch ----------------
__device__ float    g_topk_w[T * K];
__device__ int      g_topk_id[T * K];
__device__ int      g_offset[E + 1];
__device__ int      g_assign_token[T * K];
__device__ int      g_row_of[T * K];
__device__ uint32_t g_hs_pk[(size_t)T * H];       // packed bf16 hi|lo<<16
__device__ uint32_t g_act_pk[(size_t)T * K * F];  // packed bf16 hi|lo<<16
__device__ float    g_y[(size_t)T * K * H];

// ---------------- helpers ----------------
__device__ __forceinline__ uint32_t smem_u32(const void* p) {
    uint32_t a;
    asm("{ .reg .u64 t; cvta.to.shared.u64 t, %1; cvt.u32.u64 %0, t; }" : "=r"(a) : "l"(p));
    return a;
}

#define LDM4(r, addr) \
    asm volatile("ldmatrix.sync.aligned.m8n8.x4.shared.b16 {%0,%1,%2,%3}, [%4];" \
        : "=r"((r)[0]), "=r"((r)[1]), "=r"((r)[2]), "=r"((r)[3]) : "r"(addr))

#define MMA16816(d, a, b0, b1) \
    asm volatile("mma.sync.aligned.m16n8k16.row.col.f32.bf16.bf16.f32 " \
        "{%0,%1,%2,%3}, {%4,%5,%6,%7}, {%8,%9}, {%0,%1,%2,%3};" \
        : "+f"((d)[0]), "+f"((d)[1]), "+f"((d)[2]), "+f"((d)[3]) \
        : "r"((a)[0]), "r"((a)[1]), "r"((a)[2]), "r"((a)[3]), "r"(b0), "r"(b1))

__device__ __forceinline__ void cvt_split4(float4 v, uint2& hi, uint2& lo) {
    uint32_t h01, h23, l01, l23;
    asm("cvt.rn.bf16x2.f32 %0, %1, %2;" : "=r"(h01) : "f"(v.y), "f"(v.x));
    asm("cvt.rn.bf16x2.f32 %0, %1, %2;" : "=r"(h23) : "f"(v.w), "f"(v.z));
    float h0 = __uint_as_float(h01 << 16), h1 = __uint_as_float(h01 & 0xFFFF0000u);
    float h2 = __uint_as_float(h23 << 16), h3 = __uint_as_float(h23 & 0xFFFF0000u);
    asm("cvt.rn.bf16x2.f32 %0, %1, %2;" : "=r"(l01) : "f"(v.y - h1), "f"(v.x - h0));
    asm("cvt.rn.bf16x2.f32 %0, %1, %2;" : "=r"(l23) : "f"(v.w - h3), "f"(v.z - h2));
    hi = make_uint2(h01, h23);
    lo = make_uint2(l01, l23);
}

__device__ __forceinline__ void unpack4(uint4 p, uint2& hi, uint2& lo) {
    hi.x = __byte_perm(p.x, p.y, 0x5410);
    hi.y = __byte_perm(p.z, p.w, 0x5410);
    lo.x = __byte_perm(p.x, p.y, 0x7632);
    lo.y = __byte_perm(p.z, p.w, 0x7632);
}

__device__ __forceinline__ uint32_t pack_hl(float a) {
    __nv_bfloat16 h = __float2bfloat16(a);
    float hf = __bfloat162float(h);
    __nv_bfloat16 l = __float2bfloat16(a - hf);
    return (uint32_t)__bfloat16_as_ushort(h) | ((uint32_t)__bfloat16_as_ushort(l) << 16);
}

__device__ __forceinline__ float silu(float x) { return x / (1.f + __expf(-x)); }

// ---------------- hs preconvert ----------------
__global__ void hs_convert_kernel(const float* __restrict__ hs) {
    int i = blockIdx.x * blockDim.x + threadIdx.x;
    float4 v = *(const float4*)(hs + (size_t)i * 4);
    uint4 p;
    p.x = pack_hl(v.x); p.y = pack_hl(v.y); p.z = pack_hl(v.z); p.w = pack_hl(v.w);
    *(uint4*)(g_hs_pk + (size_t)i * 4) = p;
}

// ---------------- router ----------------
__global__ void router_kernel(const float* __restrict__ hs,
                              const float* __restrict__ gw) {
    int warp = (blockIdx.x * blockDim.x + threadIdx.x) >> 5;
    int lane = threadIdx.x & 31;
    if (warp >= T) return;

    const float4* x4 = (const float4*)(hs + (size_t)warp * H);
    const float4* g4 = (const float4*)(gw + (size_t)lane * H);
    float acc = 0.f;
#pragma unroll 4
    for (int i = 0; i < H / 4; i++) {
        float4 xv = x4[i];
        float4 gv = g4[i];
        acc += xv.x * gv.x + xv.y * gv.y + xv.z * gv.z + xv.w * gv.w;
    }
    float m = acc;
#pragma unroll
    for (int o = 16; o; o >>= 1) m = fmaxf(m, __shfl_xor_sync(0xffffffffu, m, o));
    float p = __expf(acc - m);
    float s = p;
#pragma unroll
    for (int o = 16; o; o >>= 1) s += __shfl_xor_sync(0xffffffffu, s, o);
    float prob = p / s;

    float cur = prob;
    float wv[K];
    int   wid[K];
#pragma unroll
    for (int k = 0; k < K; k++) {
        float v = cur;
        int who = lane;
#pragma unroll
        for (int o = 16; o; o >>= 1) {
            float ov = __shfl_xor_sync(0xffffffffu, v, o);
            int   oi = __shfl_xor_sync(0xffffffffu, who, o);
            if (ov > v || (ov == v && oi < who)) { v = ov; who = oi; }
        }
        wv[k] = v;
        wid[k] = who;
        if (lane == who) cur = -1.f;
    }
    if (lane == 0) {
        float ws = wv[0] + wv[1] + wv[2] + wv[3];
        float inv = 1.f / ws;
#pragma unroll
        for (int k = 0; k < K; k++) {
            g_topk_w[warp * K + k]  = wv[k] * inv;
            g_topk_id[warp * K + k] = wid[k];
        }
    }
}

// ---------------- bucket: count + scan + scatter in one block ----------------
__global__ void bucket_kernel() {
    __shared__ int cnt[E];
    __shared__ int curp[E];
    __shared__ int offp[E + 1];
    int t = threadIdx.x;
    if (t < E) cnt[t] = 0;
    __syncthreads();
    int ids[K];
#pragma unroll
    for (int k = 0; k < K; k++) {
        ids[k] = g_topk_id[t * K + k];
        atomicAdd(&cnt[ids[k]], 1);
    }
    __syncthreads();
    if (t == 0) {
        int a = 0;
        for (int e = 0; e < E; e++) { offp[e] = a; curp[e] = a; a += cnt[e]; }
        offp[E] = a;
    }
    __syncthreads();
#pragma unroll
    for (int k = 0; k < K; k++) {
        int pos = atomicAdd(&curp[ids[k]], 1);
        g_assign_token[pos] = t;
        g_row_of[t * K + k] = pos;
    }
    if (t <= E) g_offset[t] = offp[t];
}

// ================= GEMM1: 4 warps, warp tile 64x64, CTA 128x128(B rows) =================
__global__ __launch_bounds__(128) void gemm1_mma(const float* __restrict__ w1) {
    const int e  = blockIdx.y >> 3;
    const int mt = blockIdx.y & 7;
    const int rbeg = g_offset[e], rend = g_offset[e + 1];
    const int row0 = rbeg + mt * 128;
    if (row0 >= rend) return;
    const int fbase = blockIdx.x * 64;

    extern __shared__ __align__(16) char smem[];

    const int tid = threadIdx.x, lane = tid & 31;
    const int wm = (tid >> 5) & 1, wn = tid >> 6;

    // A staging roles: 128 rows x 8 uint4-slots = 1024 units, 8/thread
    const uint32_t* aptr[8];
    uint32_t aoff[8];
#pragma unroll
    for (int i = 0; i < 8; i++) {
        int unit = tid + i * 128;
        int j = unit >> 3, s = unit & 7;
        int rr = row0 + j;
        int tok = g_assign_token[rr < rend ? rr : rbeg];
        aptr[i] = g_hs_pk + (size_t)tok * H + s * 4;
        aoff[i] = (uint32_t)(j * PITCH_B + s * 8);
    }
    // B staging roles: 128 interleaved B-rows x 8 float4-quads, 8/thread
    const float* bptr[8];
    uint32_t boff[8];
#pragma unroll
    for (int i = 0; i < 8; i++) {
        int unit = tid + i * 128;
        int n = unit >> 3, q = unit & 7;
        int j = n >> 1, s = n & 1;
        size_t grow = (size_t)e * (2 * F) + (s ? F : 0) + fbase + j;
        bptr[i] = w1 + grow * H + q * 4;
        boff[i] = (uint32_t)(n * PITCH_B + q * 8);
    }

    const uint32_t base = smem_u32(smem);

    float acc[32][4];
#pragma unroll
    for (int i = 0; i < 32; i++)
#pragma unroll
        for (int j = 0; j < 4; j++) acc[i][j] = 0.f;

    // stage chunk 0 into buf 0
#pragma unroll
    for (int i = 0; i < 8; i++) {
        uint2 hi, lo;
        unpack4(*(const uint4*)aptr[i], hi, lo);
        *(uint2*)(smem + aoff[i]) = hi;
        *(uint2*)(smem + PLANE + aoff[i]) = lo;
        cvt_split4(*(const float4*)bptr[i], hi, lo);
        *(uint2*)(smem + 2 * PLANE + boff[i]) = hi;
        *(uint2*)(smem + 3 * PLANE + boff[i]) = lo;
    }
    __syncthreads();

    for (int c = 0; c < NC1; c++) {
        const uint32_t cb = base + (c & 1) * BUF_STRIDE;
        char* nbp = smem + ((c + 1) & 1) * BUF_STRIDE;

#pragma unroll
        for (int ks = 0; ks < 2; ks++) {
            const uint32_t kb = ks * 32;
            const uint32_t lrow = (lane & 15), lcol = (lane >> 4) * 16;
            uint32_t ah[4][4], al[4][4];
#pragma unroll
            for (int i = 0; i < 4; i++) {
                uint32_t off = (uint32_t)((wm * 64 + i * 16 + lrow) * PITCH_B) + lcol + kb;
                LDM4(ah[i], cb + off);
                LDM4(al[i], cb + PLANE + off);
            }
            uint32_t bh[4][4], bl[4][4];
#pragma unroll
            for (int j2 = 0; j2 < 4; j2++) {
                uint32_t off = (uint32_t)((wn * 64 + j2 * 16 + lrow) * PITCH_B) + lcol + kb;
                LDM4(bh[j2], cb + 2 * PLANE + off);
                LDM4(bl[j2], cb + 3 * PLANE + off);
            }
            // pass-major MMAs: 32 independent per pass
#pragma unroll
            for (int i = 0; i < 4; i++)
#pragma unroll
                for (int jt = 0; jt < 8; jt++) {
                    int j2 = jt >> 1, hsel = jt & 1;
                    MMA16816(acc[i * 8 + jt], ah[i], bh[j2][hsel], bh[j2][2 + hsel]);
                }
#pragma unroll
            for (int i = 0; i < 4; i++)
#pragma unroll
                for (int jt = 0; jt < 8; jt++) {
                    int j2 = jt >> 1, hsel = jt & 1;
                    MMA16816(acc[i * 8 + jt], ah[i], bl[j2][hsel], bl[j2][2 + hsel]);
                }
#pragma unroll
            for (int i = 0; i < 4; i++)
#pragma unroll
                for (int jt = 0; jt < 8; jt++) {
                    int j2 = jt >> 1, hsel = jt & 1;
                    MMA16816(acc[i * 8 + jt], al[i], bh[j2][hsel], bh[j2][2 + hsel]);
                }
        }

        if (c + 1 < NC1) {
            const int ko = (c + 1) * KC;
#pragma unroll
            for (int i = 0; i < 8; i++) {
                uint2 hi, lo;
                unpack4(*(const uint4*)(aptr[i] + ko), hi, lo);
                *(uint2*)(nbp + aoff[i]) = hi;
                *(uint2*)(nbp + PLANE + aoff[i]) = lo;
                cvt_split4(*(const float4*)(bptr[i] + ko), hi, lo);
                *(uint2*)(nbp + 2 * PLANE + boff[i]) = hi;
                *(uint2*)(nbp + 3 * PLANE + boff[i]) = lo;
            }
        }
        __syncthreads();
    }

    // epilogue: (c0,c1)=(g,u) row r1; (c2,c3)=(g,u) row r1+8
#pragma unroll
    for (int i = 0; i < 4; i++)
#pragma unroll
        for (int jt = 0; jt < 8; jt++) {
            float* d = acc[i * 8 + jt];
            int f = fbase + wn * 32 + jt * 4 + (lane & 3);
            int r1 = row0 + wm * 64 + i * 16 + (lane >> 2);
            float a0 = silu(d[0]) * d[1];
            float a1 = silu(d[2]) * d[3];
            if (r1 < rend)     g_act_pk[(size_t)r1 * F + f] = pack_hl(a0);
            if (r1 + 8 < rend) g_act_pk[(size_t)(r1 + 8) * F + f] = pack_hl(a1);
        }
}

// ================= GEMM2: 4 warps, warp tile 64x64, CTA 128x128 =================
__global__ __launch_bounds__(128) void gemm2_mma(const float* __restrict__ w2) {
    const int e  = blockIdx.y >> 3;
    const int mt = blockIdx.y & 7;
    const int rbeg = g_offset[e], rend = g_offset[e + 1];
    const int row0 = rbeg + mt * 128;
    if (row0 >= rend) return;
    const int hbase = blockIdx.x * 128;

    extern __shared__ __align__(16) char smem[];

    const int tid = threadIdx.x, lane = tid & 31;
    const int wm = (tid >> 5) & 1, wn = tid >> 6;

    const uint32_t* aptr[8];
    uint32_t aoff[8];
#pragma unroll
    for (int i = 0; i < 8; i++) {
        int unit = tid + i * 128;
        int j = unit >> 3, s = unit & 7;
        int rr = row0 + j;
        int row = rr < rend ? rr : rbeg;
        aptr[i] = g_act_pk + (size_t)row * F + s * 4;
        aoff[i] = (uint32_t)(j * PITCH_B + s * 8);
    }
    const float* bptr[8];
    uint32_t boff[8];
#pragma unroll
    for (int i = 0; i < 8; i++) {
        int unit = tid + i * 128;
        int n = unit >> 3, q = unit & 7;
        bptr[i] = w2 + ((size_t)e * H + hbase + n) * F + q * 4;
        boff[i] = (uint32_t)(n * PITCH_B + q * 8);
    }

    const uint32_t base = smem_u32(smem);

    float acc[32][4];
#pragma unroll
    for (int i = 0; i < 32; i++)
#pragma unroll
        for (int j = 0; j < 4; j++) acc[i][j] = 0.f;

#pragma unroll
    for (int i = 0; i < 8; i++) {
        uint2 hi, lo;
        unpack4(*(const uint4*)aptr[i], hi, lo);
        *(uint2*)(smem + aoff[i]) = hi;
        *(uint2*)(smem + PLANE + aoff[i]) = lo;
        cvt_split4(*(const float4*)bptr[i], hi, lo);
        *(uint2*)(smem + 2 * PLANE + boff[i]) = hi;
        *(uint2*)(smem + 3 * PLANE + boff[i]) = lo;
    }
    __syncthreads();

    for (int c = 0; c < NC2; c++) {
        const uint32_t cb = base + (c & 1) * BUF_STRIDE;
        char* nbp = smem + ((c + 1) & 1) * BUF_STRIDE;

#pragma unroll
        for (int ks = 0; ks < 2; ks++) {
            const uint32_t kb = ks * 32;
            const uint32_t lrow = (lane & 15), lcol = (lane >> 4) * 16;
            uint32_t ah[4][4], al[4][4];
#pragma unroll
            for (int i = 0; i < 4; i++) {
                uint32_t off = (uint32_t)((wm * 64 + i * 16 + lrow) * PITCH_B) + lcol + kb;
                LDM4(ah[i], cb + off);
                LDM4(al[i], cb + PLANE + off);
            }
            uint32_t bh[4][4], bl[4][4];
#pragma unroll
            for (int j2 = 0; j2 < 4; j2++) {
                uint32_t off = (uint32_t)((wn * 64 + j2 * 16 + lrow) * PITCH_B) + lcol + kb;
                LDM4(bh[j2], cb + 2 * PLANE + off);
                LDM4(bl[j2], cb + 3 * PLANE + off);
            }
#pragma unroll
            for (int i = 0; i < 4; i++)
#pragma unroll
                for (int jt = 0; jt < 8; jt++) {
                    int j2 = jt >> 1, hsel = jt & 1;
                    MMA16816(acc[i * 8 + jt], ah[i], bh[j2][hsel], bh[j2][2 + hsel]);
                }
#pragma unroll
            for (int i = 0; i < 4; i++)
#pragma unroll
                for (int jt = 0; jt < 8; jt++) {
                    int j2 = jt >> 1, hsel = jt & 1;
                    MMA16816(acc[i * 8 + jt], ah[i], bl[j2][hsel], bl[j2][2 + hsel]);
                }
#pragma unroll
            for (int i = 0; i < 4; i++)
#pragma unroll
                for (int jt = 0; jt < 8; jt++) {
                    int j2 = jt >> 1, hsel = jt & 1;
                    MMA16816(acc[i * 8 + jt], al[i], bh[j2][hsel], bh[j2][2 + hsel]);
                }
        }

        if (c + 1 < NC2) {
            const int ko = (c + 1) * KC;
#pragma unroll
            for (int i = 0; i < 8; i++) {
                uint2 hi, lo;
                unpack4(*(const uint4*)(aptr[i] + ko), hi, lo);
                *(uint2*)(nbp + aoff[i]) = hi;
                *(uint2*)(nbp + PLANE + aoff[i]) = lo;
                cvt_split4(*(const float4*)(bptr[i] + ko), hi, lo);
                *(uint2*)(nbp + 2 * PLANE + boff[i]) = hi;
                *(uint2*)(nbp + 3 * PLANE + boff[i]) = lo;
            }
        }
        __syncthreads();
    }

#pragma unroll
    for (int i = 0; i < 4; i++)
#pragma unroll
        for (int jt = 0; jt < 8; jt++) {
            float* d = acc[i * 8 + jt];
            int hcol = hbase + wn * 64 + jt * 8 + 2 * (lane & 3);
            int r1 = row0 + wm * 64 + i * 16 + (lane >> 2);
            if (r1 < rend)
                *(float2*)(g_y + (size_t)r1 * H + hcol) = make_float2(d[0], d[1]);
            if (r1 + 8 < rend)
                *(float2*)(g_y + (size_t)(r1 + 8) * H + hcol) = make_float2(d[2], d[3]);
        }
}

// ---------------- gather ----------------
__global__ void gather_kernel(float* __restrict__ out) {
    int t = blockIdx.x;
    __shared__ float ws[K];
    __shared__ int   rs[K];
    if (threadIdx.x < K) {
        ws[threadIdx.x] = g_topk_w[t * K + threadIdx.x];
        rs[threadIdx.x] = g_row_of[t * K + threadIdx.x];
    }
    __syncthreads();
    int h = threadIdx.x * 4;
    float4 acc = make_float4(0.f, 0.f, 0.f, 0.f);
#pragma unroll
    for (int k = 0; k < K; k++) {
        float4 v = *(const float4*)(g_y + (size_t)rs[k] * H + h);
        float w = ws[k];
        acc.x += w * v.x;
        acc.y += w * v.y;
        acc.z += w * v.z;
        acc.w += w * v.w;
    }
    *(float4*)(out + (size_t)t * H + h) = acc;
}

extern "C" void kernel_launch(void* const* d_in, const int* in_sizes, int n_in,
                              void* d_out, int out_size) {
    const float* hs = (const float*)d_in[0];
    const float* gw = (const float*)d_in[1];
    const float* w1 = (const float*)d_in[2];
    const float* w2 = (const float*)d_in[3];
    float* out = (float*)d_out;

    static bool attr_done = false;
    if (!attr_done) {
        cudaFuncSetAttribute(gemm1_mma, cudaFuncAttributeMaxDynamicSharedMemorySize, SMEM_TOTAL);
        cudaFuncSetAttribute(gemm2_mma, cudaFuncAttributeMaxDynamicSharedMemorySize, SMEM_TOTAL);
        attr_done = true;
    }

    hs_convert_kernel<<<T * H / 4 / 256, 256>>>(hs);
    router_kernel<<<T / 4, 128>>>(hs, gw);
    bucket_kernel<<<1, 1024>>>();
    gemm1_mma<<<dim3(F / 64, E * 8), 128, SMEM_TOTAL>>>(w1);
    gemm2_mma<<<dim3(H / 128, E * 8), 128, SMEM_TOTAL>>>(w2);
    gather_kernel<<<T, 256>>>(out);
}

// round 9
// speedup vs baseline: 1.4054x; 1.1217x over previous
#include <cuda_runtime.h>
#include <cuda.h>
#include <cuda_bf16.h>
#include <cstdint>
#include <dlfcn.h>

#define T 1024
#define H 1024
#define F 768
#define E 32
#define K 4

#define MAXTILES 64
#define PITCH 80
#define PLANE 10240          /* 128*80 */
#define APAIR 20480          /* hi+lo planes */
#define NC1 32
#define NC2 24
#define A1_TILE (NC1*APAIR)
#define ACT_TILE (NC2*APAIR)

// smem layout
#define OFF_MBAR 0
#define OFF_AP   1024                   /* 2 slots x APAIR */
#define OFF_BP   (OFF_AP + 2*APAIR)     /* 1 x APAIR (converted B) */
#define OFF_RAW  (OFF_BP + APAIR)       /* 2 slots x 16384 raw fp32 B */
#define SMEM_TOTAL (OFF_RAW + 2*16384)  /* 95232 */
#define TX_ALL (APAIR + 16384)

// ---------------- scratch ----------------
__device__ float    g_topk_w[T * K];
__device__ int      g_topk_id[T * K];
__device__ int      g_offset[E + 1];
__device__ int      g_tile_base[E];
__device__ int      g_row_of[T * K];
__device__ __align__(16) char g_A1[(size_t)MAXTILES * A1_TILE];
__device__ __align__(16) char g_act[(size_t)MAXTILES * ACT_TILE];
__device__ float    g_y[(size_t)T * K * H];

// ---------------- helpers ----------------
__device__ __forceinline__ uint32_t smem_u32(const void* p) {
    uint32_t a;
    asm("{ .reg .u64 t; cvta.to.shared.u64 t, %1; cvt.u32.u64 %0, t; }" : "=r"(a) : "l"(p));
    return a;
}

#define MBAR_INIT(a, c) \
    asm volatile("mbarrier.init.shared.b64 [%0], %1;" :: "r"((uint32_t)(a)), "r"((uint32_t)(c)) : "memory")
#define MBAR_EXPECT(a, tx) \
    asm volatile("mbarrier.arrive.expect_tx.shared.b64 _, [%0], %1;" :: "r"((uint32_t)(a)), "r"((uint32_t)(tx)) : "memory")
#define MBAR_WAIT(a, ph) do { \
    asm volatile("{\n\t.reg .pred P;\n\tWL%=:\n\t" \
        "mbarrier.try_wait.parity.acquire.cta.shared::cta.b64 P, [%0], %1, 0x989680;\n\t" \
        "@P bra.uni WD%=;\n\tbra.uni WL%=;\n\tWD%=:\n\t}" \
        :: "r"((uint32_t)(a)), "r"((uint32_t)(ph)) : "memory"); } while (0)
#define BULK_G2S(dst, src, sz, mb) \
    asm volatile("cp.async.bulk.shared::cluster.global.mbarrier::complete_tx::bytes [%0], [%1], %2, [%3];" \
        :: "r"((uint32_t)(dst)), "l"(src), "r"((uint32_t)(sz)), "r"((uint32_t)(mb)) : "memory")
#define TMA2D(dst, map, x, y, mb) \
    asm volatile("cp.async.bulk.tensor.2d.shared::cta.global.tile.mbarrier::complete_tx::bytes " \
        "[%0], [%1, {%2, %3}], [%4];" \
        :: "r"((uint32_t)(dst)), "l"(map), "r"((int)(x)), "r"((int)(y)), "r"((uint32_t)(mb)) : "memory")

#define LDM4(r, addr) \
    asm volatile("ldmatrix.sync.aligned.m8n8.x4.shared.b16 {%0,%1,%2,%3}, [%4];" \
        : "=r"((r)[0]), "=r"((r)[1]), "=r"((r)[2]), "=r"((r)[3]) : "r"(addr))

#define MMA16816(d, a, b0, b1) \
    asm volatile("mma.sync.aligned.m16n8k16.row.col.f32.bf16.bf16.f32 " \
        "{%0,%1,%2,%3}, {%4,%5,%6,%7}, {%8,%9}, {%0,%1,%2,%3};" \
        : "+f"((d)[0]), "+f"((d)[1]), "+f"((d)[2]), "+f"((d)[3]) \
        : "r"((a)[0]), "r"((a)[1]), "r"((a)[2]), "r"((a)[3]), "r"(b0), "r"(b1))

__device__ __forceinline__ void cvt_split4(float4 v, uint2& hi, uint2& lo) {
    uint32_t h01, h23, l01, l23;
    asm("cvt.rn.bf16x2.f32 %0, %1, %2;" : "=r"(h01) : "f"(v.y), "f"(v.x));
    asm("cvt.rn.bf16x2.f32 %0, %1, %2;" : "=r"(h23) : "f"(v.w), "f"(v.z));
    float h0 = __uint_as_float(h01 << 16), h1 = __uint_as_float(h01 & 0xFFFF0000u);
    float h2 = __uint_as_float(h23 << 16), h3 = __uint_as_float(h23 & 0xFFFF0000u);
    asm("cvt.rn.bf16x2.f32 %0, %1, %2;" : "=r"(l01) : "f"(v.y - h1), "f"(v.x - h0));
    asm("cvt.rn.bf16x2.f32 %0, %1, %2;" : "=r"(l23) : "f"(v.w - h3), "f"(v.z - h2));
    hi = make_uint2(h01, h23);
    lo = make_uint2(l01, l23);
}

__device__ __forceinline__ float silu(float x) { return x / (1.f + __expf(-x)); }

// ---------------- router ----------------
__global__ void router_kernel(const float* __restrict__ hs,
                              const float* __restrict__ gw) {
    int warp = (blockIdx.x * blockDim.x + threadIdx.x) >> 5;
    int lane = threadIdx.x & 31;
    if (warp >= T) return;

    const float4* x4 = (const float4*)(hs + (size_t)warp * H);
    const float4* g4 = (const float4*)(gw + (size_t)lane * H);
    float acc = 0.f;
#pragma unroll 4
    for (int i = 0; i < H / 4; i++) {
        float4 xv = x4[i];
        float4 gv = g4[i];
        acc += xv.x * gv.x + xv.y * gv.y + xv.z * gv.z + xv.w * gv.w;
    }
    float m = acc;
#pragma unroll
    for (int o = 16; o; o >>= 1) m = fmaxf(m, __shfl_xor_sync(0xffffffffu, m, o));
    float p = __expf(acc - m);
    float s = p;
#pragma unroll
    for (int o = 16; o; o >>= 1) s += __shfl_xor_sync(0xffffffffu, s, o);
    float prob = p / s;

    float cur = prob;
    float wv[K];
    int   wid[K];
#pragma unroll
    for (int k = 0; k < K; k++) {
        float v = cur;
        int who = lane;
#pragma unroll
        for (int o = 16; o; o >>= 1) {
            float ov = __shfl_xor_sync(0xffffffffu, v, o);
            int   oi = __shfl_xor_sync(0xffffffffu, who, o);
            if (ov > v || (ov == v && oi < who)) { v = ov; who = oi; }
        }
        wv[k] = v;
        wid[k] = who;
        if (lane == who) cur = -1.f;
    }
    if (lane == 0) {
        float ws = wv[0] + wv[1] + wv[2] + wv[3];
        float inv = 1.f / ws;
#pragma unroll
        for (int k = 0; k < K; k++) {
            g_topk_w[warp * K + k]  = wv[k] * inv;
            g_topk_id[warp * K + k] = wid[k];
        }
    }
}

// ---------------- bucket ----------------
__global__ void bucket_kernel() {
    __shared__ int cnt[E];
    __shared__ int curp[E];
    __shared__ int offp[E + 1];
    int t = threadIdx.x;
    if (t < E) cnt[t] = 0;
    __syncthreads();
    int ids[K];
#pragma unroll
    for (int k = 0; k < K; k++) {
        ids[k] = g_topk_id[t * K + k];
        atomicAdd(&cnt[ids[k]], 1);
    }
    __syncthreads();
    if (t == 0) {
        int a = 0, tb = 0;
        for (int e = 0; e < E; e++) {
            offp[e] = a; curp[e] = a; a += cnt[e];
            g_tile_base[e] = tb; tb += (cnt[e] + 127) >> 7;
        }
        offp[E] = a;
    }
    __syncthreads();
#pragma unroll
    for (int k = 0; k < K; k++) {
        int pos = atomicAdd(&curp[ids[k]], 1);
        g_row_of[t * K + k] = pos;
    }
    if (t <= E) g_offset[t] = offp[t];
}

// ---------------- hs -> chunked hi/lo planes ----------------
__global__ void hs_chunk_kernel(const float* __restrict__ hs) {
    int t = blockIdx.x;
    __shared__ int dtile[K], djj[K];
    if (threadIdx.x < K) {
        int r = g_row_of[t * K + threadIdx.x];
        int e = g_topk_id[t * K + threadIdx.x];
        int j = r - g_offset[e];
        dtile[threadIdx.x] = g_tile_base[e] + (j >> 7);
        djj[threadIdx.x] = j & 127;
    }
    __syncthreads();
    int u = threadIdx.x;
    int c = u >> 2, p = u & 3;
    int k0 = c * 32 + p * 8;
    float4 v0 = *(const float4*)(hs + (size_t)t * H + k0);
    float4 v1 = *(const float4*)(hs + (size_t)t * H + k0 + 4);
    uint2 h0, l0, h1, l1;
    cvt_split4(v0, h0, l0);
    cvt_split4(v1, h1, l1);
    uint4 hv = make_uint4(h0.x, h0.y, h1.x, h1.y);
    uint4 lv = make_uint4(l0.x, l0.y, l1.x, l1.y);
#pragma unroll
    for (int k = 0; k < K; k++) {
        char* base = g_A1 + (size_t)dtile[k] * A1_TILE + c * APAIR + djj[k] * PITCH + p * 16;
        *(uint4*)base = hv;
        *(uint4*)(base + PLANE) = lv;
    }
}

// ---------------- shared GEMM pieces ----------------
__device__ __forceinline__ void convert_b(char* smem, int slot, int tid) {
    const char* rp = smem + OFF_RAW + slot * 16384 + tid * 128;
    char* hp = smem + OFF_BP + tid * PITCH;
#pragma unroll
    for (int q = 0; q < 8; q++) {
        int qq = (q + tid) & 7;
        float4 v = *(const float4*)(rp + qq * 16);
        uint2 hi, lo;
        cvt_split4(v, hi, lo);
        *(uint2*)(hp + qq * 8) = hi;
        *(uint2*)(hp + PLANE + qq * 8) = lo;
    }
}

__device__ __forceinline__ void mma_phase(uint32_t sb, int slot, int lane, int wm,
                                          const int brow[4], float acc[32][4]) {
    const uint32_t Ah = sb + OFF_AP + slot * APAIR;
    const uint32_t Bh = sb + OFF_BP;
#pragma unroll
    for (int ks = 0; ks < 2; ks++) {
        const uint32_t kb = ks * 32;
        const uint32_t lrow = (lane & 15), lcol = (lane >> 4) * 16;
        uint32_t ah[4][4], al[4][4];
#pragma unroll
        for (int i = 0; i < 4; i++) {
            uint32_t off = (uint32_t)((wm * 64 + i * 16 + lrow) * PITCH) + lcol + kb;
            LDM4(ah[i], Ah + off);
            LDM4(al[i], Ah + PLANE + off);
        }
        uint32_t bh[4][4], bl[4][4];
#pragma unroll
        for (int j2 = 0; j2 < 4; j2++) {
            uint32_t off = (uint32_t)((brow[j2] + lrow) * PITCH) + lcol + kb;
            LDM4(bh[j2], Bh + off);
            LDM4(bl[j2], Bh + PLANE + off);
        }
#pragma unroll
        for (int i = 0; i < 4; i++)
#pragma unroll
            for (int jt = 0; jt < 8; jt++) {
                int j2 = jt >> 1, hsel = jt & 1;
                MMA16816(acc[i * 8 + jt], ah[i], bh[j2][hsel], bh[j2][2 + hsel]);
            }
#pragma unroll
        for (int i = 0; i < 4; i++)
#pragma unroll
            for (int jt = 0; jt < 8; jt++) {
                int j2 = jt >> 1, hsel = jt & 1;
                MMA16816(acc[i * 8 + jt], ah[i], bl[j2][hsel], bl[j2][2 + hsel]);
            }
#pragma unroll
        for (int i = 0; i < 4; i++)
#pragma unroll
            for (int jt = 0; jt < 8; jt++) {
                int j2 = jt >> 1, hsel = jt & 1;
                MMA16816(acc[i * 8 + jt], al[i], bh[j2][hsel], bh[j2][2 + hsel]);
            }
    }
}

// stage chunk cc into slot (cc&1): tid0 only
__device__ __forceinline__ void stage_chunk(uint32_t sb, const char* asrc, int cc,
                                            const CUtensorMap* bmap, int y0, int y1,
                                            bool split) {
    int slot = cc & 1;
    uint32_t fb = sb + OFF_MBAR + slot * 8;
    MBAR_EXPECT(fb, TX_ALL);
    BULK_G2S(sb + OFF_AP + slot * APAIR, asrc + (size_t)cc * APAIR, APAIR, fb);
    uint32_t raw = sb + OFF_RAW + slot * 16384;
    if (split) {
        TMA2D(raw, bmap, cc * 32, y0, fb);
        TMA2D(raw + 8192, bmap, cc * 32, y1, fb);
    } else {
        TMA2D(raw, bmap, cc * 32, y0, fb);
    }
}

__device__ __forceinline__ void gemm_mainloop(char* smem, uint32_t sb, int tid, int lane,
                                              int wm, const int brow[4], const char* asrc,
                                              const CUtensorMap* bmap, int y0, int y1,
                                              bool split, int nc, float acc[32][4]) {
    if (tid == 0) {
        MBAR_INIT(sb + OFF_MBAR, 1);
        MBAR_INIT(sb + OFF_MBAR + 8, 1);
    }
    __syncthreads();
    if (tid == 0) {
        stage_chunk(sb, asrc, 0, bmap, y0, y1, split);
        stage_chunk(sb, asrc, 1, bmap, y0, y1, split);
    }
    for (int c = 0; c < nc; c++) {
        int slot = c & 1;
        MBAR_WAIT(sb + OFF_MBAR + slot * 8, (c >> 1) & 1);
        convert_b(smem, slot, tid);
        __syncthreads();
        mma_phase(sb, slot, lane, wm, brow, acc);
        __syncthreads();
        if (tid == 0 && c + 2 < nc)
            stage_chunk(sb, asrc, c + 2, bmap, y0, y1, split);
    }
}

// ================= GEMM1 =================
__global__ __launch_bounds__(128, 2) void gemm1_mma(const __grid_constant__ CUtensorMap bmap) {
    const int e  = blockIdx.y >> 3;
    const int mt = blockIdx.y & 7;
    const int rbeg = g_offset[e], rend = g_offset[e + 1];
    const int row0 = rbeg + mt * 128;
    if (row0 >= rend) return;
    const int fbase = blockIdx.x * 64;
    const int tile = g_tile_base[e] + mt;

    extern __shared__ __align__(16) char smem[];
    const uint32_t sb = smem_u32(smem);
    const int tid = threadIdx.x, lane = tid & 31;
    const int wm = (tid >> 5) & 1, wn = tid >> 6;

    // B rows: RAW 0..63 = gate f=fbase+j, 64..127 = up
    int brow[4];
#pragma unroll
    for (int j2 = 0; j2 < 4; j2++)
        brow[j2] = (j2 < 2) ? (wn * 32 + j2 * 16) : (64 + wn * 32 + (j2 - 2) * 16);

    const char* asrc = g_A1 + (size_t)tile * A1_TILE;
    const int y0 = e * 2 * F + fbase;       // gate rows
    const int y1 = e * 2 * F + F + fbase;   // up rows

    float acc[32][4];
#pragma unroll
    for (int i = 0; i < 32; i++)
#pragma unroll
        for (int j = 0; j < 4; j++) acc[i][j] = 0.f;

    gemm_mainloop(smem, sb, tid, lane, wm, brow, asrc, &bmap, y0, y1, true, NC1, acc);

    // epilogue: silu(g)*u -> hi/lo planes staged in smem (reuse AP), then linear copy
    char* stage = smem + OFF_AP;
#pragma unroll
    for (int i = 0; i < 4; i++)
#pragma unroll
        for (int jt = 0; jt < 4; jt++) {
            float* dg = acc[i * 8 + jt];
            float* du = acc[i * 8 + jt + 4];
            int fl = wn * 32 + jt * 8 + 2 * (lane & 3);
            int cf = fl >> 5, c32 = fl & 31;
            int j1 = wm * 64 + i * 16 + (lane >> 2);
#pragma unroll
            for (int rs = 0; rs < 2; rs++) {
                float a0 = silu(dg[rs * 2 + 0]) * du[rs * 2 + 0];
                float a1 = silu(dg[rs * 2 + 1]) * du[rs * 2 + 1];
                uint32_t hp, lp;
                asm("cvt.rn.bf16x2.f32 %0, %1, %2;" : "=r"(hp) : "f"(a1), "f"(a0));
                float hh0 = __uint_as_float(hp << 16), hh1 = __uint_as_float(hp & 0xFFFF0000u);
                asm("cvt.rn.bf16x2.f32 %0, %1, %2;" : "=r"(lp) : "f"(a1 - hh1), "f"(a0 - hh0));
                char* p0 = stage + cf * APAIR + (j1 + rs * 8) * PITCH + c32 * 2;
                *(uint32_t*)p0 = hp;
                *(uint32_t*)(p0 + PLANE) = lp;
            }
        }
    __syncthreads();
    char* dst = g_act + (size_t)tile * ACT_TILE + (size_t)(fbase >> 5) * APAIR;
#pragma unroll
    for (int i = 0; i < 20; i++) {
        int idx = tid + i * 128;
        *(uint4*)(dst + (size_t)idx * 16) = *(const uint4*)(stage + idx * 16);
    }
}

// ================= GEMM2 =================
__global__ __launch_bounds__(128, 2) void gemm2_mma(const __grid_constant__ CUtensorMap bmap) {
    const int e  = blockIdx.y >> 3;
    const int mt = blockIdx.y & 7;
    const int rbeg = g_offset[e], rend = g_offset[e + 1];
    const int row0 = rbeg + mt * 128;
    if (row0 >= rend) return;
    const int hbase = blockIdx.x * 128;
    const int tile = g_tile_base[e] + mt;

    extern __shared__ __align__(16) char smem[];
    const uint32_t sb = smem_u32(smem);
    const int tid = threadIdx.x, lane = tid & 31;
    const int wm = (tid >> 5) & 1, wn = tid >> 6;

    int brow[4];
#pragma unroll
    for (int j2 = 0; j2 < 4; j2++) brow[j2] = wn * 64 + j2 * 16;

    const char* asrc = g_act + (size_t)tile * ACT_TILE;
    const int y0 = e * H + hbase;

    float acc[32][4];
#pragma unroll
    for (int i = 0; i < 32; i++)
#pragma unroll
        for (int j = 0; j < 4; j++) acc[i][j] = 0.f;

    gemm_mainloop(smem, sb, tid, lane, wm, brow, asrc, &bmap, y0, 0, false, NC2, acc);

#pragma unroll
    for (int i = 0; i < 4; i++)
#pragma unroll
        for (int jt = 0; jt < 8; jt++) {
            float* d = acc[i * 8 + jt];
            int hcol = hbase + wn * 64 + jt * 8 + 2 * (lane & 3);
            int r1 = row0 + wm * 64 + i * 16 + (lane >> 2);
            if (r1 < rend)
                *(float2*)(g_y + (size_t)r1 * H + hcol) = make_float2(d[0], d[1]);
            if (r1 + 8 < rend)
                *(float2*)(g_y + (size_t)(r1 + 8) * H + hcol) = make_float2(d[2], d[3]);
        }
}

// ---------------- gather ----------------
__global__ void gather_kernel(float* __restrict__ out) {
    int t = blockIdx.x;
    __shared__ float ws[K];
    __shared__ int   rs[K];
    if (threadIdx.x < K) {
        ws[threadIdx.x] = g_topk_w[t * K + threadIdx.x];
        rs[threadIdx.x] = g_row_of[t * K + threadIdx.x];
    }
    __syncthreads();
    int h = threadIdx.x * 4;
    float4 acc = make_float4(0.f, 0.f, 0.f, 0.f);
#pragma unroll
    for (int k = 0; k < K; k++) {
        float4 v = *(const float4*)(g_y + (size_t)rs[k] * H + h);
        float w = ws[k];
        acc.x += w * v.x;
        acc.y += w * v.y;
        acc.z += w * v.z;
        acc.w += w * v.w;
    }
    *(float4*)(out + (size_t)t * H + h) = acc;
}

// ---------------- host ----------------
typedef CUresult (*encode_fn_t)(CUtensorMap*, CUtensorMapDataType, cuuint32_t, void*,
                                const cuuint64_t*, const cuuint64_t*, const cuuint32_t*,
                                const cuuint32_t*, CUtensorMapInterleave, CUtensorMapSwizzle,
                                CUtensorMapL2promotion, CUtensorMapFloatOOBfill);

extern "C" void kernel_launch(void* const* d_in, const int* in_sizes, int n_in,
                              void* d_out, int out_size) {
    const float* hs = (const float*)d_in[0];
    const float* gw = (const float*)d_in[1];
    const float* w1 = (const float*)d_in[2];
    const float* w2 = (const float*)d_in[3];
    float* out = (float*)d_out;

    static encode_fn_t enc = nullptr;
    static bool attr_done = false;
    if (!attr_done) {
        cudaFuncSetAttribute(gemm1_mma, cudaFuncAttributeMaxDynamicSharedMemorySize, SMEM_TOTAL);
        cudaFuncSetAttribute(gemm2_mma, cudaFuncAttributeMaxDynamicSharedMemorySize, SMEM_TOTAL);
        void* hlib = dlopen("libcuda.so.1", RTLD_NOW | RTLD_GLOBAL);
        if (!hlib) hlib = dlopen("libcuda.so", RTLD_NOW | RTLD_GLOBAL);
        if (hlib) enc = (encode_fn_t)dlsym(hlib, "cuTensorMapEncodeTiled");
        attr_done = true;
    }

    // tensormaps (deterministic per call; device pointers are constant across calls)
    CUtensorMap m1, m2;
    {
        cuuint64_t dims[2] = {(cuuint64_t)H, (cuuint64_t)E * 2 * F};
        cuuint64_t strides[1] = {(cuuint64_t)H * 4};
        cuuint32_t box[2] = {32, 64};
        cuuint32_t es[2] = {1, 1};
        enc(&m1, CU_TENSOR_MAP_DATA_TYPE_FLOAT32, 2, (void*)w1, dims, strides, box, es,
            CU_TENSOR_MAP_INTERLEAVE_NONE, CU_TENSOR_MAP_SWIZZLE_NONE,
            CU_TENSOR_MAP_L2_PROMOTION_L2_128B, CU_TENSOR_MAP_FLOAT_OOB_FILL_NONE);
    }
    {
        cuuint64_t dims[2] = {(cuuint64_t)F, (cuuint64_t)E * H};
        cuuint64_t strides[1] = {(cuuint64_t)F * 4};
        cuuint32_t box[2] = {32, 128};
        cuuint32_t es[2] = {1, 1};
        enc(&m2, CU_TENSOR_MAP_DATA_TYPE_FLOAT32, 2, (void*)w2, dims, strides, box, es,
            CU_TENSOR_MAP_INTERLEAVE_NONE, CU_TENSOR_MAP_SWIZZLE_NONE,
            CU_TENSOR_MAP_L2_PROMOTION_L2_128B, CU_TENSOR_MAP_FLOAT_OOB_FILL_NONE);
    }

    router_kernel<<<T / 4, 128>>>(hs, gw);
    bucket_kernel<<<1, 1024>>>();
    hs_chunk_kernel<<<T, 128>>>(hs);
    gemm1_mma<<<dim3(F / 64, E * 8), 128, SMEM_TOTAL>>>(m1);
    gemm2_mma<<<dim3(H / 128, E * 8), 128, SMEM_TOTAL>>>(m2);
    gather_kernel<<<T, 256>>>(out);
}

// round 10
// speedup vs baseline: 1.4417x; 1.0259x over previous
#include <cuda_runtime.h>
#include <cuda.h>
#include <cuda_bf16.h>
#include <cstdint>
#include <dlfcn.h>

#define T 1024
#define H 1024
#define F 768
#define E 32
#define K 4

#define MAXTILES 64
#define PITCH 80
#define PLANE 10240          /* 128*80 */
#define APAIR 20480          /* hi+lo planes */
#define NC1 32
#define NC2 24
#define A1_TILE (NC1*APAIR)
#define ACT_TILE (NC2*APAIR)

// smem layout
#define OFF_MBAR 0
#define OFF_AP   1024                   /* 2 slots x APAIR */
#define OFF_BP   (OFF_AP + 2*APAIR)     /* 2 slots x APAIR (converted B) */
#define OFF_RAW  (OFF_BP + 2*APAIR)     /* 2 slots x 16384 raw fp32 B */
#define SMEM_TOTAL (OFF_RAW + 2*16384)  /* 115712 */
#define TX_ALL (APAIR + 16384)

// ---------------- scratch ----------------
__device__ float    g_topk_w[T * K];
__device__ int      g_topk_id[T * K];
__device__ int      g_offset[E + 1];
__device__ int      g_tile_base[E];
__device__ int      g_row_of[T * K];
__device__ __align__(16) char g_A1[(size_t)MAXTILES * A1_TILE];
__device__ __align__(16) char g_act[(size_t)MAXTILES * ACT_TILE];
__device__ float    g_y[(size_t)T * K * H];

// ---------------- helpers ----------------
__device__ __forceinline__ uint32_t smem_u32(const void* p) {
    uint32_t a;
    asm("{ .reg .u64 t; cvta.to.shared.u64 t, %1; cvt.u32.u64 %0, t; }" : "=r"(a) : "l"(p));
    return a;
}

#define MBAR_INIT(a, c) \
    asm volatile("mbarrier.init.shared.b64 [%0], %1;" :: "r"((uint32_t)(a)), "r"((uint32_t)(c)) : "memory")
#define MBAR_EXPECT(a, tx) \
    asm volatile("mbarrier.arrive.expect_tx.shared.b64 _, [%0], %1;" :: "r"((uint32_t)(a)), "r"((uint32_t)(tx)) : "memory")
#define MBAR_WAIT(a, ph) do { \
    asm volatile("{\n\t.reg .pred P;\n\tWL%=:\n\t" \
        "mbarrier.try_wait.parity.acquire.cta.shared::cta.b64 P, [%0], %1, 0x989680;\n\t" \
        "@P bra.uni WD%=;\n\tbra.uni WL%=;\n\tWD%=:\n\t}" \
        :: "r"((uint32_t)(a)), "r"((uint32_t)(ph)) : "memory"); } while (0)
#define BULK_G2S(dst, src, sz, mb) \
    asm volatile("cp.async.bulk.shared::cluster.global.mbarrier::complete_tx::bytes [%0], [%1], %2, [%3];" \
        :: "r"((uint32_t)(dst)), "l"(src), "r"((uint32_t)(sz)), "r"((uint32_t)(mb)) : "memory")
#define TMA2D(dst, map, x, y, mb) \
    asm volatile("cp.async.bulk.tensor.2d.shared::cta.global.tile.mbarrier::complete_tx::bytes " \
        "[%0], [%1, {%2, %3}], [%4];" \
        :: "r"((uint32_t)(dst)), "l"(map), "r"((int)(x)), "r"((int)(y)), "r"((uint32_t)(mb)) : "memory")

#define LDM4(r, addr) \
    asm volatile("ldmatrix.sync.aligned.m8n8.x4.shared.b16 {%0,%1,%2,%3}, [%4];" \
        : "=r"((r)[0]), "=r"((r)[1]), "=r"((r)[2]), "=r"((r)[3]) : "r"(addr))

#define MMA16816(d, a, b0, b1) \
    asm volatile("mma.sync.aligned.m16n8k16.row.col.f32.bf16.bf16.f32 " \
        "{%0,%1,%2,%3}, {%4,%5,%6,%7}, {%8,%9}, {%0,%1,%2,%3};" \
        : "+f"((d)[0]), "+f"((d)[1]), "+f"((d)[2]), "+f"((d)[3]) \
        : "r"((a)[0]), "r"((a)[1]), "r"((a)[2]), "r"((a)[3]), "r"(b0), "r"(b1))

__device__ __forceinline__ void cvt_split4(float4 v, uint2& hi, uint2& lo) {
    uint32_t h01, h23, l01, l23;
    asm("cvt.rn.bf16x2.f32 %0, %1, %2;" : "=r"(h01) : "f"(v.y), "f"(v.x));
    asm("cvt.rn.bf16x2.f32 %0, %1, %2;" : "=r"(h23) : "f"(v.w), "f"(v.z));
    float h0 = __uint_as_float(h01 << 16), h1 = __uint_as_float(h01 & 0xFFFF0000u);
    float h2 = __uint_as_float(h23 << 16), h3 = __uint_as_float(h23 & 0xFFFF0000u);
    asm("cvt.rn.bf16x2.f32 %0, %1, %2;" : "=r"(l01) : "f"(v.y - h1), "f"(v.x - h0));
    asm("cvt.rn.bf16x2.f32 %0, %1, %2;" : "=r"(l23) : "f"(v.w - h3), "f"(v.z - h2));
    hi = make_uint2(h01, h23);
    lo = make_uint2(l01, l23);
}

__device__ __forceinline__ float silu(float x) { return x / (1.f + __expf(-x)); }

// ---------------- router ----------------
__global__ void router_kernel(const float* __restrict__ hs,
                              const float* __restrict__ gw) {
    int warp = (blockIdx.x * blockDim.x + threadIdx.x) >> 5;
    int lane = threadIdx.x & 31;
    if (warp >= T) return;

    const float4* x4 = (const float4*)(hs + (size_t)warp * H);
    const float4* g4 = (const float4*)(gw + (size_t)lane * H);
    float acc = 0.f;
#pragma unroll 4
    for (int i = 0; i < H / 4; i++) {
        float4 xv = x4[i];
        float4 gv = g4[i];
        acc += xv.x * gv.x + xv.y * gv.y + xv.z * gv.z + xv.w * gv.w;
    }
    float m = acc;
#pragma unroll
    for (int o = 16; o; o >>= 1) m = fmaxf(m, __shfl_xor_sync(0xffffffffu, m, o));
    float p = __expf(acc - m);
    float s = p;
#pragma unroll
    for (int o = 16; o; o >>= 1) s += __shfl_xor_sync(0xffffffffu, s, o);
    float prob = p / s;

    float cur = prob;
    float wv[K];
    int   wid[K];
#pragma unroll
    for (int k = 0; k < K; k++) {
        float v = cur;
        int who = lane;
#pragma unroll
        for (int o = 16; o; o >>= 1) {
            float ov = __shfl_xor_sync(0xffffffffu, v, o);
            int   oi = __shfl_xor_sync(0xffffffffu, who, o);
            if (ov > v || (ov == v && oi < who)) { v = ov; who = oi; }
        }
        wv[k] = v;
        wid[k] = who;
        if (lane == who) cur = -1.f;
    }
    if (lane == 0) {
        float ws = wv[0] + wv[1] + wv[2] + wv[3];
        float inv = 1.f / ws;
#pragma unroll
        for (int k = 0; k < K; k++) {
            g_topk_w[warp * K + k]  = wv[k] * inv;
            g_topk_id[warp * K + k] = wid[k];
        }
    }
}

// ---------------- bucket ----------------
__global__ void bucket_kernel() {
    __shared__ int cnt[E];
    __shared__ int curp[E];
    __shared__ int offp[E + 1];
    int t = threadIdx.x;
    if (t < E) cnt[t] = 0;
    __syncthreads();
    int ids[K];
#pragma unroll
    for (int k = 0; k < K; k++) {
        ids[k] = g_topk_id[t * K + k];
        atomicAdd(&cnt[ids[k]], 1);
    }
    __syncthreads();
    if (t == 0) {
        int a = 0, tb = 0;
        for (int e = 0; e < E; e++) {
            offp[e] = a; curp[e] = a; a += cnt[e];
            g_tile_base[e] = tb; tb += (cnt[e] + 127) >> 7;
        }
        offp[E] = a;
    }
    __syncthreads();
#pragma unroll
    for (int k = 0; k < K; k++) {
        int pos = atomicAdd(&curp[ids[k]], 1);
        g_row_of[t * K + k] = pos;
    }
    if (t <= E) g_offset[t] = offp[t];
}

// ---------------- hs -> chunked hi/lo planes ----------------
__global__ void hs_chunk_kernel(const float* __restrict__ hs) {
    int t = blockIdx.x;
    __shared__ int dtile[K], djj[K];
    if (threadIdx.x < K) {
        int r = g_row_of[t * K + threadIdx.x];
        int e = g_topk_id[t * K + threadIdx.x];
        int j = r - g_offset[e];
        dtile[threadIdx.x] = g_tile_base[e] + (j >> 7);
        djj[threadIdx.x] = j & 127;
    }
    __syncthreads();
    int u = threadIdx.x;
    int c = u >> 2, p = u & 3;
    int k0 = c * 32 + p * 8;
    float4 v0 = *(const float4*)(hs + (size_t)t * H + k0);
    float4 v1 = *(const float4*)(hs + (size_t)t * H + k0 + 4);
    uint2 h0, l0, h1, l1;
    cvt_split4(v0, h0, l0);
    cvt_split4(v1, h1, l1);
    uint4 hv = make_uint4(h0.x, h0.y, h1.x, h1.y);
    uint4 lv = make_uint4(l0.x, l0.y, l1.x, l1.y);
#pragma unroll
    for (int k = 0; k < K; k++) {
        char* base = g_A1 + (size_t)dtile[k] * A1_TILE + c * APAIR + djj[k] * PITCH + p * 16;
        *(uint4*)base = hv;
        *(uint4*)(base + PLANE) = lv;
    }
}

// ---------------- shared GEMM pieces ----------------
__device__ __forceinline__ void convert_b(char* smem, int slot, int tid) {
    const char* rp = smem + OFF_RAW + slot * 16384 + tid * 128;
    char* hp = smem + OFF_BP + slot * APAIR + tid * PITCH;
#pragma unroll
    for (int q = 0; q < 8; q++) {
        int qq = (q + tid) & 7;
        float4 v = *(const float4*)(rp + qq * 16);
        uint2 hi, lo;
        cvt_split4(v, hi, lo);
        *(uint2*)(hp + qq * 8) = hi;
        *(uint2*)(hp + PLANE + qq * 8) = lo;
    }
}

__device__ __forceinline__ void mma_phase(uint32_t sb, int slot, int lane, int wm,
                                          const int brow[4], float acc[32][4]) {
    const uint32_t Ah = sb + OFF_AP + slot * APAIR;
    const uint32_t Bh = sb + OFF_BP + slot * APAIR;
#pragma unroll
    for (int ks = 0; ks < 2; ks++) {
        const uint32_t kb = ks * 32;
        const uint32_t lrow = (lane & 15), lcol = (lane >> 4) * 16;
        uint32_t ah[4][4], al[4][4];
#pragma unroll
        for (int i = 0; i < 4; i++) {
            uint32_t off = (uint32_t)((wm * 64 + i * 16 + lrow) * PITCH) + lcol + kb;
            LDM4(ah[i], Ah + off);
            LDM4(al[i], Ah + PLANE + off);
        }
        uint32_t bh[4][4], bl[4][4];
#pragma unroll
        for (int j2 = 0; j2 < 4; j2++) {
            uint32_t off = (uint32_t)((brow[j2] + lrow) * PITCH) + lcol + kb;
            LDM4(bh[j2], Bh + off);
            LDM4(bl[j2], Bh + PLANE + off);
        }
#pragma unroll
        for (int i = 0; i < 4; i++)
#pragma unroll
            for (int jt = 0; jt < 8; jt++) {
                int j2 = jt >> 1, hsel = jt & 1;
                MMA16816(acc[i * 8 + jt], ah[i], bh[j2][hsel], bh[j2][2 + hsel]);
            }
#pragma unroll
        for (int i = 0; i < 4; i++)
#pragma unroll
            for (int jt = 0; jt < 8; jt++) {
                int j2 = jt >> 1, hsel = jt & 1;
                MMA16816(acc[i * 8 + jt], ah[i], bl[j2][hsel], bl[j2][2 + hsel]);
            }
#pragma unroll
        for (int i = 0; i < 4; i++)
#pragma unroll
            for (int jt = 0; jt < 8; jt++) {
                int j2 = jt >> 1, hsel = jt & 1;
                MMA16816(acc[i * 8 + jt], al[i], bh[j2][hsel], bh[j2][2 + hsel]);
            }
    }
}

// stage chunk cc into slot (cc&1): tid0 only
__device__ __forceinline__ void stage_chunk(uint32_t sb, const char* asrc, int cc,
                                            const CUtensorMap* bmap, int y0, int y1,
                                            bool split) {
    int slot = cc & 1;
    uint32_t fb = sb + OFF_MBAR + slot * 8;
    MBAR_EXPECT(fb, TX_ALL);
    BULK_G2S(sb + OFF_AP + slot * APAIR, asrc + (size_t)cc * APAIR, APAIR, fb);
    uint32_t raw = sb + OFF_RAW + slot * 16384;
    if (split) {
        TMA2D(raw, bmap, cc * 32, y0, fb);
        TMA2D(raw + 8192, bmap, cc * 32, y1, fb);
    } else {
        TMA2D(raw, bmap, cc * 32, y0, fb);
    }
}

// fused pipeline: MMA(c) overlaps wait+convert(c+1); one sync per iter
__device__ __forceinline__ void gemm_mainloop(char* smem, uint32_t sb, int tid, int lane,
                                              int wm, const int brow[4], const char* asrc,
                                              const CUtensorMap* bmap, int y0, int y1,
                                              bool split, int nc, float acc[32][4]) {
    if (tid == 0) {
        MBAR_INIT(sb + OFF_MBAR, 1);
        MBAR_INIT(sb + OFF_MBAR + 8, 1);
    }
    __syncthreads();
    if (tid == 0) {
        stage_chunk(sb, asrc, 0, bmap, y0, y1, split);
        stage_chunk(sb, asrc, 1, bmap, y0, y1, split);
    }
    // preamble: chunk0 converted before first MMA
    MBAR_WAIT(sb + OFF_MBAR, 0);
    convert_b(smem, 0, tid);
    __syncthreads();

    for (int c = 0; c < nc; c++) {
        int slot = c & 1;
        mma_phase(sb, slot, lane, wm, brow, acc);     // tensor pipe drains async
        if (c + 1 < nc) {                              // overlap: wait+convert next chunk
            int ns = (c + 1) & 1;
            MBAR_WAIT(sb + OFF_MBAR + ns * 8, ((c + 1) >> 1) & 1);
            convert_b(smem, ns, tid);
        }
        __syncthreads();                               // AP[slot]/raw reads done; BP[ns] visible
        if (tid == 0 && c + 2 < nc)
            stage_chunk(sb, asrc, c + 2, bmap, y0, y1, split);
    }
}

// ================= GEMM1 =================
__global__ __launch_bounds__(128, 1) void gemm1_mma(const __grid_constant__ CUtensorMap bmap) {
    const int e  = blockIdx.y >> 3;
    const int mt = blockIdx.y & 7;
    const int rbeg = g_offset[e], rend = g_offset[e + 1];
    const int row0 = rbeg + mt * 128;
    if (row0 >= rend) return;
    const int fbase = blockIdx.x * 64;
    const int tile = g_tile_base[e] + mt;

    extern __shared__ __align__(16) char smem[];
    const uint32_t sb = smem_u32(smem);
    const int tid = threadIdx.x, lane = tid & 31;
    const int wm = (tid >> 5) & 1, wn = tid >> 6;

    int brow[4];
#pragma unroll
    for (int j2 = 0; j2 < 4; j2++)
        brow[j2] = (j2 < 2) ? (wn * 32 + j2 * 16) : (64 + wn * 32 + (j2 - 2) * 16);

    const char* asrc = g_A1 + (size_t)tile * A1_TILE;
    const int y0 = e * 2 * F + fbase;
    const int y1 = e * 2 * F + F + fbase;

    float acc[32][4];
#pragma unroll
    for (int i = 0; i < 32; i++)
#pragma unroll
        for (int j = 0; j < 4; j++) acc[i][j] = 0.f;

    gemm_mainloop(smem, sb, tid, lane, wm, brow, asrc, &bmap, y0, y1, true, NC1, acc);

    __syncthreads();
    char* stage = smem + OFF_AP;
#pragma unroll
    for (int i = 0; i < 4; i++)
#pragma unroll
        for (int jt = 0; jt < 4; jt++) {
            float* dg = acc[i * 8 + jt];
            float* du = acc[i * 8 + jt + 4];
            int fl = wn * 32 + jt * 8 + 2 * (lane & 3);
            int cf = fl >> 5, c32 = fl & 31;
            int j1 = wm * 64 + i * 16 + (lane >> 2);
#pragma unroll
            for (int rs = 0; rs < 2; rs++) {
                float a0 = silu(dg[rs * 2 + 0]) * du[rs * 2 + 0];
                float a1 = silu(dg[rs * 2 + 1]) * du[rs * 2 + 1];
                uint32_t hp, lp;
                asm("cvt.rn.bf16x2.f32 %0, %1, %2;" : "=r"(hp) : "f"(a1), "f"(a0));
                float hh0 = __uint_as_float(hp << 16), hh1 = __uint_as_float(hp & 0xFFFF0000u);
                asm("cvt.rn.bf16x2.f32 %0, %1, %2;" : "=r"(lp) : "f"(a1 - hh1), "f"(a0 - hh0));
                char* p0 = stage + cf * APAIR + (j1 + rs * 8) * PITCH + c32 * 2;
                *(uint32_t*)p0 = hp;
                *(uint32_t*)(p0 + PLANE) = lp;
            }
        }
    __syncthreads();
    char* dst = g_act + (size_t)tile * ACT_TILE + (size_t)(fbase >> 5) * APAIR;
#pragma unroll
    for (int i = 0; i < 20; i++) {
        int idx = tid + i * 128;
        *(uint4*)(dst + (size_t)idx * 16) = *(const uint4*)(stage + idx * 16);
    }
}

// ================= GEMM2 =================
__global__ __launch_bounds__(128, 1) void gemm2_mma(const __grid_constant__ CUtensorMap bmap) {
    const int e  = blockIdx.y >> 3;
    const int mt = blockIdx.y & 7;
    const int rbeg = g_offset[e], rend = g_offset[e + 1];
    const int row0 = rbeg + mt * 128;
    if (row0 >= rend) return;
    const int hbase = blockIdx.x * 128;
    const int tile = g_tile_base[e] + mt;

    extern __shared__ __align__(16) char smem[];
    const uint32_t sb = smem_u32(smem);
    const int tid = threadIdx.x, lane = tid & 31;
    const int wm = (tid >> 5) & 1, wn = tid >> 6;

    int brow[4];
#pragma unroll
    for (int j2 = 0; j2 < 4; j2++) brow[j2] = wn * 64 + j2 * 16;

    const char* asrc = g_act + (size_t)tile * ACT_TILE;
    const int y0 = e * H + hbase;

    float acc[32][4];
#pragma unroll
    for (int i = 0; i < 32; i++)
#pragma unroll
        for (int j = 0; j < 4; j++) acc[i][j] = 0.f;

    gemm_mainloop(smem, sb, tid, lane, wm, brow, asrc, &bmap, y0, 0, false, NC2, acc);

#pragma unroll
    for (int i = 0; i < 4; i++)
#pragma unroll
        for (int jt = 0; jt < 8; jt++) {
            float* d = acc[i * 8 + jt];
            int hcol = hbase + wn * 64 + jt * 8 + 2 * (lane & 3);
            int r1 = row0 + wm * 64 + i * 16 + (lane >> 2);
            if (r1 < rend)
                *(float2*)(g_y + (size_t)r1 * H + hcol) = make_float2(d[0], d[1]);
            if (r1 + 8 < rend)
                *(float2*)(g_y + (size_t)(r1 + 8) * H + hcol) = make_float2(d[2], d[3]);
        }
}

// ---------------- gather ----------------
__global__ void gather_kernel(float* __restrict__ out) {
    int t = blockIdx.x;
    __shared__ float ws[K];
    __shared__ int   rs[K];
    if (threadIdx.x < K) {
        ws[threadIdx.x] = g_topk_w[t * K + threadIdx.x];
        rs[threadIdx.x] = g_row_of[t * K + threadIdx.x];
    }
    __syncthreads();
    int h = threadIdx.x * 4;
    float4 acc = make_float4(0.f, 0.f, 0.f, 0.f);
#pragma unroll
    for (int k = 0; k < K; k++) {
        float4 v = *(const float4*)(g_y + (size_t)rs[k] * H + h);
        float w = ws[k];
        acc.x += w * v.x;
        acc.y += w * v.y;
        acc.z += w * v.z;
        acc.w += w * v.w;
    }
    *(float4*)(out + (size_t)t * H + h) = acc;
}

// ---------------- host ----------------
typedef CUresult (*encode_fn_t)(CUtensorMap*, CUtensorMapDataType, cuuint32_t, void*,
                                const cuuint64_t*, const cuuint64_t*, const cuuint32_t*,
                                const cuuint32_t*, CUtensorMapInterleave, CUtensorMapSwizzle,
                                CUtensorMapL2promotion, CUtensorMapFloatOOBfill);

extern "C" void kernel_launch(void* const* d_in, const int* in_sizes, int n_in,
                              void* d_out, int out_size) {
    const float* hs = (const float*)d_in[0];
    const float* gw = (const float*)d_in[1];
    const float* w1 = (const float*)d_in[2];
    const float* w2 = (const float*)d_in[3];
    float* out = (float*)d_out;

    static encode_fn_t enc = nullptr;
    static bool attr_done = false;
    if (!attr_done) {
        cudaFuncSetAttribute(gemm1_mma, cudaFuncAttributeMaxDynamicSharedMemorySize, SMEM_TOTAL);
        cudaFuncSetAttribute(gemm2_mma, cudaFuncAttributeMaxDynamicSharedMemorySize, SMEM_TOTAL);
        void* hlib = dlopen("libcuda.so.1", RTLD_NOW | RTLD_GLOBAL);
        if (!hlib) hlib = dlopen("libcuda.so", RTLD_NOW | RTLD_GLOBAL);
        if (hlib) enc = (encode_fn_t)dlsym(hlib, "cuTensorMapEncodeTiled");
        attr_done = true;
    }

    CUtensorMap m1, m2;
    {
        cuuint64_t dims[2] = {(cuuint64_t)H, (cuuint64_t)E * 2 * F};
        cuuint64_t strides[1] = {(cuuint64_t)H * 4};
        cuuint32_t box[2] = {32, 64};
        cuuint32_t es[2] = {1, 1};
        enc(&m1, CU_TENSOR_MAP_DATA_TYPE_FLOAT32, 2, (void*)w1, dims, strides, box, es,
            CU_TENSOR_MAP_INTERLEAVE_NONE, CU_TENSOR_MAP_SWIZZLE_NONE,
            CU_TENSOR_MAP_L2_PROMOTION_L2_128B, CU_TENSOR_MAP_FLOAT_OOB_FILL_NONE);
    }
    {
        cuuint64_t dims[2] = {(cuuint64_t)F, (cuuint64_t)E * H};
        cuuint64_t strides[1] = {(cuuint64_t)F * 4};
        cuuint32_t box[2] = {32, 128};
        cuuint32_t es[2] = {1, 1};
        enc(&m2, CU_TENSOR_MAP_DATA_TYPE_FLOAT32, 2, (void*)w2, dims, strides, box, es,
            CU_TENSOR_MAP_INTERLEAVE_NONE, CU_TENSOR_MAP_SWIZZLE_NONE,
            CU_TENSOR_MAP_L2_PROMOTION_L2_128B, CU_TENSOR_MAP_FLOAT_OOB_FILL_NONE);
    }

    router_kernel<<<T / 4, 128>>>(hs, gw);
    bucket_kernel<<<1, 1024>>>();
    hs_chunk_kernel<<<T, 128>>>(hs);
    gemm1_mma<<<dim3(F / 64, E * 8), 128, SMEM_TOTAL>>>(m1);
    gemm2_mma<<<dim3(H / 128, E * 8), 128, SMEM_TOTAL>>>(m2);
    gather_kernel<<<T, 256>>>(out);
}